// round 3
// baseline (speedup 1.0000x reference)
#include <cuda_runtime.h>
#include <cstdint>

// Problem dims
#define B_  8
#define LQ_ 512
#define LK_ 512
#define D_  512
#define H_  128

// Scratch for projected q and k: [B*LQ, H] and [B*LK, H]
__device__ float g_q[B_ * LQ_ * H_];
__device__ float g_k[B_ * LK_ * H_];

__device__ __forceinline__ float tanh_fast(float x) {
    float y;
    asm("tanh.approx.f32 %0, %1;" : "=f"(y) : "f"(x));
    return y;
}

// ---------------------------------------------------------------------------
// Projection GEMM: Y[m, h] = sum_d X[m, d] * W[d, h]
// M = 4096 (= B*L), K = 512, N = 128.
// CTA tile: 32 x 128, 256 threads, 4x4 outputs per thread, K-chunk 32.
// blockIdx.y: 0 -> (qs, Wq, g_q), 1 -> (ks, Wk, g_k)
// ---------------------------------------------------------------------------
__global__ __launch_bounds__(256) void proj_kernel(
    const float* __restrict__ qs, const float* __restrict__ ks,
    const float* __restrict__ Wq, const float* __restrict__ Wk)
{
    const float* X = blockIdx.y ? ks : qs;
    const float* W = blockIdx.y ? Wk : Wq;
    float* Y       = blockIdx.y ? g_k : g_q;

    __shared__ float As[32][32];    // 4 KB
    __shared__ float Bs[32][128];   // 16 KB

    const int tid = threadIdx.x;        // 0..255
    const int tx  = tid & 31;           // n-group: n0 = tx*4
    const int ty  = tid >> 5;           // m-group: m0 = ty*4 (0..7)
    const int m_base = blockIdx.x * 32;

    float acc[4][4];
#pragma unroll
    for (int i = 0; i < 4; i++)
#pragma unroll
        for (int j = 0; j < 4; j++) acc[i][j] = 0.0f;

    for (int k0 = 0; k0 < D_; k0 += 32) {
        // Load A tile: 32x32 floats = 256 float4, one per thread.
        {
            int row = tid >> 3;           // 0..31
            int c4  = tid & 7;            // 0..7
            float4 v = *reinterpret_cast<const float4*>(
                &X[(size_t)(m_base + row) * D_ + k0 + c4 * 4]);
            *reinterpret_cast<float4*>(&As[row][c4 * 4]) = v;
        }
        // Load B tile: 32x128 floats = 1024 float4, four per thread.
#pragma unroll
        for (int l = 0; l < 4; l++) {
            int idx = l * 256 + tid;      // 0..1023
            int row = idx >> 5;           // 0..31
            int c4  = idx & 31;           // 0..31
            float4 v = *reinterpret_cast<const float4*>(
                &W[(size_t)(k0 + row) * H_ + c4 * 4]);
            *reinterpret_cast<float4*>(&Bs[row][c4 * 4]) = v;
        }
        __syncthreads();

#pragma unroll
        for (int kk = 0; kk < 32; kk++) {
            float4 b = *reinterpret_cast<const float4*>(&Bs[kk][tx * 4]);
            float a0 = As[ty * 4 + 0][kk];
            float a1 = As[ty * 4 + 1][kk];
            float a2 = As[ty * 4 + 2][kk];
            float a3 = As[ty * 4 + 3][kk];
            acc[0][0] += a0 * b.x; acc[0][1] += a0 * b.y; acc[0][2] += a0 * b.z; acc[0][3] += a0 * b.w;
            acc[1][0] += a1 * b.x; acc[1][1] += a1 * b.y; acc[1][2] += a1 * b.z; acc[1][3] += a1 * b.w;
            acc[2][0] += a2 * b.x; acc[2][1] += a2 * b.y; acc[2][2] += a2 * b.z; acc[2][3] += a2 * b.w;
            acc[3][0] += a3 * b.x; acc[3][1] += a3 * b.y; acc[3][2] += a3 * b.z; acc[3][3] += a3 * b.w;
        }
        __syncthreads();
    }

    // Store 4x4 per thread as float4 rows.
#pragma unroll
    for (int i = 0; i < 4; i++) {
        float4 v = make_float4(acc[i][0], acc[i][1], acc[i][2], acc[i][3]);
        *reinterpret_cast<float4*>(
            &Y[(size_t)(m_base + ty * 4 + i) * H_ + tx * 4]) = v;
    }
}

// ---------------------------------------------------------------------------
// Scoring kernel: out[b,i,j] = sum_h wv[h] * tanh(q[b,i,h] + k[b,j,h])
// CTA tile: 64 (i) x 64 (j), 256 threads, each computes 4x4 outputs.
// Smem tiles padded to row stride 132 floats for conflict-free LDS.128.
// ---------------------------------------------------------------------------
#define TSTRIDE 132
#define SCORE_SMEM_BYTES ((2 * 64 * TSTRIDE + H_) * 4)

__global__ __launch_bounds__(256, 3) void score_kernel(
    const float* __restrict__ wv, float* __restrict__ out)
{
    extern __shared__ float smem[];
    float* Qs  = smem;                    // [64][132]
    float* Ks  = smem + 64 * TSTRIDE;     // [64][132]
    float* sWv = smem + 2 * 64 * TSTRIDE; // [128]

    const int tid = threadIdx.x;          // 0..255
    const int tx  = tid & 15;             // j-lane: j = jj*16 + tx
    const int ty  = tid >> 4;             // i-group: i0 = ty*4 (0..15)

    const int jt = blockIdx.x;            // j tile (0..7)
    const int it = blockIdx.y;            // i tile (0..7)
    const int b  = blockIdx.z;            // batch

    const float* qsrc = &g_q[((size_t)b * LQ_ + it * 64) * H_];
    const float* ksrc = &g_k[((size_t)b * LK_ + jt * 64) * H_];

    // Load Q and K tiles: 64 rows x 128 h each = 2048 float4 per tile.
#pragma unroll
    for (int l = 0; l < 8; l++) {
        int idx = l * 256 + tid;          // 0..2047
        int row = idx >> 5;               // 0..63
        int h4  = idx & 31;               // 0..31
        float4 q = *reinterpret_cast<const float4*>(&qsrc[(size_t)row * H_ + h4 * 4]);
        float4 k = *reinterpret_cast<const float4*>(&ksrc[(size_t)row * H_ + h4 * 4]);
        *reinterpret_cast<float4*>(&Qs[row * TSTRIDE + h4 * 4]) = q;
        *reinterpret_cast<float4*>(&Ks[row * TSTRIDE + h4 * 4]) = k;
    }
    if (tid < H_) sWv[tid] = wv[tid];
    __syncthreads();

    float acc[4][4];
#pragma unroll
    for (int i = 0; i < 4; i++)
#pragma unroll
        for (int j = 0; j < 4; j++) acc[i][j] = 0.0f;

#pragma unroll 2
    for (int h = 0; h < H_; h += 4) {
        float4 wv4 = *reinterpret_cast<const float4*>(&sWv[h]);
        float4 q[4], k[4];
#pragma unroll
        for (int ii = 0; ii < 4; ii++)
            q[ii] = *reinterpret_cast<const float4*>(&Qs[(ty * 4 + ii) * TSTRIDE + h]);
#pragma unroll
        for (int jj = 0; jj < 4; jj++)
            k[jj] = *reinterpret_cast<const float4*>(&Ks[(jj * 16 + tx) * TSTRIDE + h]);

#pragma unroll
        for (int ii = 0; ii < 4; ii++) {
#pragma unroll
            for (int jj = 0; jj < 4; jj++) {
                float s;
                s  = wv4.x * tanh_fast(q[ii].x + k[jj].x);
                s += wv4.y * tanh_fast(q[ii].y + k[jj].y);
                s += wv4.z * tanh_fast(q[ii].z + k[jj].z);
                s += wv4.w * tanh_fast(q[ii].w + k[jj].w);
                acc[ii][jj] += s;
            }
        }
    }

    // Write out: out[b][it*64 + ty*4+ii][jt*64 + jj*16+tx]
    float* obase = &out[((size_t)b * LQ_ + it * 64 + ty * 4) * LK_ + jt * 64];
#pragma unroll
    for (int ii = 0; ii < 4; ii++) {
#pragma unroll
        for (int jj = 0; jj < 4; jj++) {
            obase[(size_t)ii * LK_ + jj * 16 + tx] = acc[ii][jj];
        }
    }
}

// ---------------------------------------------------------------------------
extern "C" void kernel_launch(void* const* d_in, const int* in_sizes, int n_in,
                              void* d_out, int out_size)
{
    const float* qs = (const float*)d_in[0];
    const float* ks = (const float*)d_in[1];
    const float* Wq = (const float*)d_in[2];
    const float* Wk = (const float*)d_in[3];
    const float* wv = (const float*)d_in[4];
    float* out = (float*)d_out;

    cudaFuncSetAttribute(score_kernel,
                         cudaFuncAttributeMaxDynamicSharedMemorySize,
                         SCORE_SMEM_BYTES);

    // Projections: grid (M/32, 2) = (128, 2)
    proj_kernel<<<dim3(128, 2), 256>>>(qs, ks, Wq, Wk);

    // Scoring: grid (LK/64, LQ/64, B) = (8, 8, 8)
    score_kernel<<<dim3(LK_ / 64, LQ_ / 64, B_), 256, SCORE_SMEM_BYTES>>>(wv, out);
}